// round 4
// baseline (speedup 1.0000x reference)
#include <cuda_runtime.h>
#include <cuda_bf16.h>
#include <cstdint>

#define NUM_E 16
#define D_IN  2048
#define D_OUT 8192
#define T_TOK 8192

// CTA tile 128(M) x 256(N), K-chunk 16. 8 warps = 2(M) x 4(N), warp tile 64x64.
#define BM 128
#define BN 256
#define BK 16
#define NCHUNK (D_IN / BK)   // 128
#define THREADS 256

// smem rows: 16 bf16 = 32B data + 16B pad = 48B stride (16B aligned; r*48 mod 128
// covers distinct 16B slots for r=0..7 -> conflict-free ldmatrix).
#define ROW_B  48
#define A_HI   0
#define A_LO   (128 * ROW_B)              // 6144
#define B_HI   (2 * 128 * ROW_B)          // 12288
#define B_LO   (B_HI + 256 * ROW_B)       // 24576
#define STAGE_B (B_LO + 256 * ROW_B)      // 36864
#define SMEM_BYTES (2 * STAGE_B)          // 73728

__device__ __forceinline__ uint32_t smem_u32_of(const void* p) {
    uint32_t a;
    asm("{ .reg .u64 t; cvta.to.shared.u64 t, %1; cvt.u32.u64 %0, t; }" : "=r"(a) : "l"(p));
    return a;
}

__device__ __forceinline__ uint32_t pack2(__nv_bfloat16 a, __nv_bfloat16 b) {
    __nv_bfloat162 t = __halves2bfloat162(a, b);
    return *reinterpret_cast<uint32_t*>(&t);
}

__device__ __forceinline__ void sts16(uint32_t addr, const uint32_t* r) {
    asm volatile("st.shared.v4.b32 [%0], {%1, %2, %3, %4};"
                 :: "r"(addr), "r"(r[0]), "r"(r[1]), "r"(r[2]), "r"(r[3]) : "memory");
}

// Split 8 consecutive fp32 into bf16 hi (16B) + residual lo (16B) and store.
__device__ __forceinline__ void split_store8(const float* v, uint32_t hi_addr, uint32_t lo_addr) {
    uint32_t h[4], l[4];
    #pragma unroll
    for (int i = 0; i < 4; i++) {
        __nv_bfloat16 h0 = __float2bfloat16(v[2 * i]);
        __nv_bfloat16 h1 = __float2bfloat16(v[2 * i + 1]);
        __nv_bfloat16 l0 = __float2bfloat16(v[2 * i] - __bfloat162float(h0));
        __nv_bfloat16 l1 = __float2bfloat16(v[2 * i + 1] - __bfloat162float(h1));
        h[i] = pack2(h0, h1);
        l[i] = pack2(l0, l1);
    }
    sts16(hi_addr, h);
    sts16(lo_addr, l);
}

__device__ __forceinline__ void ldsm_x4(uint32_t* r, uint32_t addr) {
    asm volatile("ldmatrix.sync.aligned.m8n8.x4.shared.b16 {%0,%1,%2,%3}, [%4];"
                 : "=r"(r[0]), "=r"(r[1]), "=r"(r[2]), "=r"(r[3]) : "r"(addr));
}

__device__ __forceinline__ void mma_bf16(float* d, const uint32_t* a, uint32_t b0, uint32_t b1) {
    asm volatile(
        "mma.sync.aligned.m16n8k16.row.col.f32.bf16.bf16.f32 "
        "{%0,%1,%2,%3}, {%4,%5,%6,%7}, {%8,%9}, {%0,%1,%2,%3};"
        : "+f"(d[0]), "+f"(d[1]), "+f"(d[2]), "+f"(d[3])
        : "r"(a[0]), "r"(a[1]), "r"(a[2]), "r"(a[3]), "r"(b0), "r"(b1));
}

__global__ __launch_bounds__(THREADS, 1)
void moe_gemm_mma2_kernel(const float* __restrict__ inp,     // [T, D_IN]
                          const float* __restrict__ weight,  // [E, D_OUT, D_IN]
                          const float* __restrict__ bias,    // [E, D_OUT]
                          const int*   __restrict__ cnt,     // [E]
                          float*       __restrict__ out)     // [T, D_OUT]
{
    extern __shared__ char smem[];
    const uint32_t sbase = smem_u32_of(smem);

    const int tid = threadIdx.x;
    const int wid = tid >> 5;
    const int lid = tid & 31;

    const int nBase = blockIdx.x * BN;
    const int mBase = blockIdx.y * BM;

    // Owning expert (each count = 512, multiple of BM)
    int e = 0;
    {
        int acc = 0;
        #pragma unroll
        for (int i = 0; i < NUM_E; i++) {
            int c = cnt[i];
            if (mBase >= acc + c) { acc += c; e = i + 1; }
        }
    }
    const float* wptr = weight + (size_t)e * D_OUT * D_IN;

    // Warp layout: 2 (M) x 4 (N); warp tile 64x64
    const int warp_m = (wid >> 2) * 64;
    const int warp_n = (wid & 3) * 64;

    // ldmatrix lane addressing (same decomposition verified in round 3)
    const int a_row = (lid & 7) + ((lid >> 3) & 1) * 8;
    const int a_ks  = ((lid >> 4) & 1) * 8;
    const int b_row = (lid & 7) + ((lid >> 4) & 1) * 8;
    const int b_ks  = ((lid >> 3) & 1) * 8;

    // Global load mapping:
    // A: 128 rows x 16 cols -> 2 float4/thread: row=tid>>1, col=(tid&1)*8 (+0,+4)
    // B: 256 rows x 16 cols -> 4 float4/thread as two 8-float groups:
    //    group0: row=tid>>1, col=(tid&1)*8 ; group1: row=128+(tid>>1), same col
    const int arow = tid >> 1;
    const int acol = (tid & 1) * 8;
    const float* aG  = inp  + (size_t)(mBase + arow) * D_IN + acol;
    const float* bG0 = wptr + (size_t)(nBase + arow) * D_IN + acol;
    const float* bG1 = wptr + (size_t)(nBase + 128 + arow) * D_IN + acol;

    const uint32_t a_st  = (uint32_t)(arow * ROW_B + acol * 2);
    const uint32_t b_st0 = (uint32_t)(arow * ROW_B + acol * 2);
    const uint32_t b_st1 = (uint32_t)((128 + arow) * ROW_B + acol * 2);

    float d[4][8][4];
    #pragma unroll
    for (int f = 0; f < 4; f++)
        #pragma unroll
        for (int n = 0; n < 8; n++)
            #pragma unroll
            for (int k = 0; k < 4; k++)
                d[f][n][k] = 0.0f;

    float aV[8], bV0[8], bV1[8];

    // ---- prologue: chunk 0 -> stage 0 ----
    #pragma unroll
    for (int q = 0; q < 2; q++) {
        *reinterpret_cast<float4*>(aV  + q * 4) = *reinterpret_cast<const float4*>(aG  + q * 4);
        *reinterpret_cast<float4*>(bV0 + q * 4) = *reinterpret_cast<const float4*>(bG0 + q * 4);
        *reinterpret_cast<float4*>(bV1 + q * 4) = *reinterpret_cast<const float4*>(bG1 + q * 4);
    }
    split_store8(aV,  sbase + A_HI + a_st,  sbase + A_LO + a_st);
    split_store8(bV0, sbase + B_HI + b_st0, sbase + B_LO + b_st0);
    split_store8(bV1, sbase + B_HI + b_st1, sbase + B_LO + b_st1);
    __syncthreads();

    for (int i = 0; i < NCHUNK; i++) {
        // prefetch next chunk into registers (latency hides under MMAs)
        if (i + 1 < NCHUNK) {
            const int kb = (i + 1) * BK;
            #pragma unroll
            for (int q = 0; q < 2; q++) {
                *reinterpret_cast<float4*>(aV  + q * 4) = *reinterpret_cast<const float4*>(aG  + kb + q * 4);
                *reinterpret_cast<float4*>(bV0 + q * 4) = *reinterpret_cast<const float4*>(bG0 + kb + q * 4);
                *reinterpret_cast<float4*>(bV1 + q * 4) = *reinterpret_cast<const float4*>(bG1 + kb + q * 4);
            }
        }

        // ---- compute on current stage ----
        const uint32_t cur = sbase + (uint32_t)(i & 1) * STAGE_B;

        uint32_t ah[4][4], al[4][4];
        #pragma unroll
        for (int f = 0; f < 4; f++) {
            uint32_t ro = (uint32_t)((warp_m + f * 16 + a_row) * ROW_B + a_ks * 2);
            ldsm_x4(ah[f], cur + A_HI + ro);
            ldsm_x4(al[f], cur + A_LO + ro);
        }
        #pragma unroll
        for (int nb = 0; nb < 4; nb++) {
            uint32_t bh[4], bl[4];
            uint32_t ro = (uint32_t)((warp_n + nb * 16 + b_row) * ROW_B + b_ks * 2);
            ldsm_x4(bh, cur + B_HI + ro);
            ldsm_x4(bl, cur + B_LO + ro);
            #pragma unroll
            for (int f = 0; f < 4; f++) {
                float* d0 = d[f][nb * 2 + 0];
                float* d1 = d[f][nb * 2 + 1];
                mma_bf16(d0, ah[f], bh[0], bh[1]);
                mma_bf16(d1, ah[f], bh[2], bh[3]);
                mma_bf16(d0, ah[f], bl[0], bl[1]);
                mma_bf16(d1, ah[f], bl[2], bl[3]);
                mma_bf16(d0, al[f], bh[0], bh[1]);
                mma_bf16(d1, al[f], bh[2], bh[3]);
            }
        }

        // ---- split + store next chunk into the other stage ----
        if (i + 1 < NCHUNK) {
            const uint32_t nxt = sbase + (uint32_t)((i + 1) & 1) * STAGE_B;
            split_store8(aV,  nxt + A_HI + a_st,  nxt + A_LO + a_st);
            split_store8(bV0, nxt + B_HI + b_st0, nxt + B_LO + b_st0);
            split_store8(bV1, nxt + B_HI + b_st1, nxt + B_LO + b_st1);
        }
        __syncthreads();
    }

    // ---- epilogue: bias + fp32 store ----
    const int g  = lid >> 2;
    const int t4 = lid & 3;
    const float* brow = bias + (size_t)e * D_OUT;
    #pragma unroll
    for (int f = 0; f < 4; f++) {
        const int row0 = mBase + warp_m + f * 16 + g;
        #pragma unroll
        for (int nf = 0; nf < 8; nf++) {
            const int col = nBase + warp_n + nf * 8 + t4 * 2;
            float2 bv = *reinterpret_cast<const float2*>(brow + col);
            float2 o0, o1;
            o0.x = d[f][nf][0] + bv.x;
            o0.y = d[f][nf][1] + bv.y;
            o1.x = d[f][nf][2] + bv.x;
            o1.y = d[f][nf][3] + bv.y;
            *reinterpret_cast<float2*>(out + (size_t)row0 * D_OUT + col) = o0;
            *reinterpret_cast<float2*>(out + (size_t)(row0 + 8) * D_OUT + col) = o1;
        }
    }
}

extern "C" void kernel_launch(void* const* d_in, const int* in_sizes, int n_in,
                              void* d_out, int out_size)
{
    const float* inp    = (const float*)d_in[0];
    const float* weight = (const float*)d_in[1];
    const float* bias   = (const float*)d_in[2];
    const int*   cnt    = (const int*)d_in[3];
    float* out = (float*)d_out;

    cudaFuncSetAttribute(moe_gemm_mma2_kernel,
                         cudaFuncAttributeMaxDynamicSharedMemorySize, SMEM_BYTES);

    dim3 grid(D_OUT / BN, T_TOK / BM);   // (32, 64)
    moe_gemm_mma2_kernel<<<grid, THREADS, SMEM_BYTES>>>(inp, weight, bias, cnt, out);
}